// round 13
// baseline (speedup 1.0000x reference)
#include <cuda_runtime.h>
#include <math.h>
#include <cstdint>

#define HH 128
#define WW 128
#define HW (HH*WW)
#define CC 64
#define OO 64
#define BB 4
#define KK 9
#define VROW 68   // words per v row ([p][c] layout): 16B-aligned, conflict-free

// Scratch (allocation-free rule: __device__ globals)
__device__ float4 g_wts[BB*KK*HW];        // per (b,k,pixel): 4 bilinear corner weights * mask
__device__ int4   g_offs[BB*KK*HW];       // per (b,k,pixel): 4 clamped corner plane-offsets
__device__ float  g_wt[KK*CC*OO];         // weight transposed to [k][c][o]
__device__ float  g_xm[(size_t)BB*HW*CC]; // x_main pixel-major [b][p][c]
__device__ float  g_wom[2*32*9*28];       // w_om pre-staged: [half][(cl*9+t)*28 + oc]

// ---- packed f32x2 helpers ----
__device__ __forceinline__ unsigned long long pk2(float lo, float hi) {
    unsigned long long r;
    asm("mov.b64 %0,{%1,%2};" : "=l"(r) : "f"(lo), "f"(hi));
    return r;
}
__device__ __forceinline__ void fma2(unsigned long long& d, unsigned long long a, unsigned long long b) {
    asm("fma.rn.f32x2 %0,%1,%2,%0;" : "+l"(d) : "l"(a), "l"(b));
}
__device__ __forceinline__ float2 up2(unsigned long long v) {
    float2 r;
    asm("mov.b64 {%0,%1},%2;" : "=f"(r.x), "=f"(r.y) : "l"(v));
    return r;
}
__device__ __forceinline__ float fast_tanh(float x) {
    float e = __expf(2.f * x);
    return 1.f - __fdividef(2.f, e + 1.f);
}
__device__ __forceinline__ float fast_sigmoid(float x) {
    return __fdividef(1.f, 1.f + __expf(-x));
}

// ---------------- kernel 0a: weight transpose [O][C][K] -> [K][C][O] ----------------
__global__ void k_wt_transpose(const float* __restrict__ w) {
    int i = blockIdx.x * 256 + threadIdx.x;
    if (i >= KK*CC*OO) return;
    int k = i >> 12;
    int r = i & 4095;
    int c = r >> 6;
    int o = r & 63;
    g_wt[i] = w[(o*CC + c)*KK + k];
}

// ---------------- kernel 0a': w_om pre-stage into smem-ready layout ----------------
__global__ void k_wom_prep(const float* __restrict__ w_om) {
    int i = blockIdx.x * 256 + threadIdx.x;
    if (i >= 2*32*9*28) return;
    int half = i / (32*9*28);
    int r = i - half*(32*9*28);
    int ct = r / 28;
    int oc = r - ct*28;
    int cl = ct / 9;
    int t  = ct - cl*9;
    float v = 0.f;
    if (oc < 27) v = w_om[(oc*CC + (half*32 + cl))*KK + t];
    g_wom[i] = v;
}

// ---------------- kernel 0b: x_main transpose [C][H][W] -> [H][W][C] ----------------
__global__ __launch_bounds__(256) void k_xm_transpose(const float* __restrict__ x) {
    __shared__ float s[64*68];
    const int tid = threadIdx.x;
    const int b = blockIdx.y;
    const int p0 = blockIdx.x << 6;
#pragma unroll
    for (int i = 0; i < 4; i++) {
        int t = (i << 8) + tid;
        int c = t >> 4, p4 = t & 15;
        float4 v = *(const float4*)(x + (((size_t)b*CC + c) << 14) + p0 + (p4 << 2));
        int base = (p4 << 2)*68 + c;
        s[base] = v.x; s[base+68] = v.y; s[base+136] = v.z; s[base+204] = v.w;
    }
    __syncthreads();
#pragma unroll
    for (int i = 0; i < 4; i++) {
        int t = (i << 8) + tid;
        int p = t >> 4, c4 = t & 15;
        float4 v = *(const float4*)&s[p*68 + (c4 << 2)];
        *(float4*)(g_xm + (((size_t)b << 14) + p0 + p)*CC + (c4 << 2)) = v;
    }
}

// ---------------- kernel 1: offset-mask conv + bilinear prep (fast transcendentals) ----------------
__global__ __launch_bounds__(128) void k_offset3(
        const float* __restrict__ x_extra,
        const float* __restrict__ pre_offset,
        const float* __restrict__ pre_sim,
        const float* __restrict__ b_om) {
    __shared__ float ws[32*9*28];
    __shared__ float xt[4*18*20];
    const int tid = threadIdx.x;
    const int b = blockIdx.z;
    const int ty = tid >> 3;
    const int tx = tid & 7;
    const int h  = (blockIdx.y << 4) + ty;
    const int w0 = (blockIdx.x << 4) + (tx << 1);
    const int gy0 = (blockIdx.y << 4) - 1;
    const int gx0 = (blockIdx.x << 4) - 1;

    unsigned long long acc[2][14];
#pragma unroll
    for (int p = 0; p < 2; p++)
#pragma unroll
        for (int j = 0; j < 14; j++) acc[p][j] = 0ULL;

    const float* xb = x_extra + (size_t)b*CC*HW;

    for (int phase = 0; phase < 2; ++phase) {
        __syncthreads();
        {
            const float4* src = (const float4*)(g_wom + phase*(32*9*28));
            float4* dst = (float4*)ws;
            for (int i = tid; i < 32*9*28/4; i += 128) dst[i] = src[i];
        }
        __syncthreads();

        for (int rnd = 0; rnd < 8; ++rnd) {
            if (rnd) __syncthreads();
            for (int idx = tid; idx < 4*324; idx += 128) {
                int cc = idx / 324;
                int rem = idx - cc*324;
                int rr = rem / 18, col = rem - rr*18;
                int gy = gy0 + rr, gx = gx0 + col;
                int c = (phase << 5) + (rnd << 2) + cc;
                xt[cc*360 + rr*20 + col] = ((unsigned)gy < HH && (unsigned)gx < WW)
                    ? __ldg(xb + ((size_t)c << 14) + gy*WW + gx) : 0.f;
            }
            __syncthreads();

#pragma unroll
            for (int cl4 = 0; cl4 < 4; ++cl4) {
                const int cl = (rnd << 2) + cl4;
                float xp[3][4];
                const int base = cl4*360 + ty*20 + (tx << 1);
#pragma unroll
                for (int rr = 0; rr < 3; rr++) {
                    float2 lo = *(const float2*)&xt[base + rr*20];
                    float2 hi = *(const float2*)&xt[base + rr*20 + 2];
                    xp[rr][0] = lo.x; xp[rr][1] = lo.y; xp[rr][2] = hi.x; xp[rr][3] = hi.y;
                }
#pragma unroll
                for (int t = 0; t < 9; t++) {
                    const int tr = t/3, tc = t%3;
                    const ulonglong2* wr = (const ulonglong2*)&ws[(cl*9 + t)*28];
                    ulonglong2 q0 = wr[0], q1 = wr[1], q2 = wr[2];
                    ulonglong2 q3 = wr[3], q4 = wr[4], q5 = wr[5], q6 = wr[6];
                    unsigned long long xd0 = pk2(xp[tr][tc],     xp[tr][tc]);
                    unsigned long long xd1 = pk2(xp[tr][tc + 1], xp[tr][tc + 1]);
                    fma2(acc[0][0],  xd0, q0.x); fma2(acc[0][1],  xd0, q0.y);
                    fma2(acc[0][2],  xd0, q1.x); fma2(acc[0][3],  xd0, q1.y);
                    fma2(acc[0][4],  xd0, q2.x); fma2(acc[0][5],  xd0, q2.y);
                    fma2(acc[0][6],  xd0, q3.x); fma2(acc[0][7],  xd0, q3.y);
                    fma2(acc[0][8],  xd0, q4.x); fma2(acc[0][9],  xd0, q4.y);
                    fma2(acc[0][10], xd0, q5.x); fma2(acc[0][11], xd0, q5.y);
                    fma2(acc[0][12], xd0, q6.x); fma2(acc[0][13], xd0, q6.y);
                    fma2(acc[1][0],  xd1, q0.x); fma2(acc[1][1],  xd1, q0.y);
                    fma2(acc[1][2],  xd1, q1.x); fma2(acc[1][3],  xd1, q1.y);
                    fma2(acc[1][4],  xd1, q2.x); fma2(acc[1][5],  xd1, q2.y);
                    fma2(acc[1][6],  xd1, q3.x); fma2(acc[1][7],  xd1, q3.y);
                    fma2(acc[1][8],  xd1, q4.x); fma2(acc[1][9],  xd1, q4.y);
                    fma2(acc[1][10], xd1, q5.x); fma2(acc[1][11], xd1, q5.y);
                    fma2(acc[1][12], xd1, q6.x); fma2(acc[1][13], xd1, q6.y);
                }
            }
        }
    }

#pragma unroll
    for (int p = 0; p < 2; p++) {
        const int wp_ = w0 + p;
        const int pix = h*WW + wp_;
        float a[28];
#pragma unroll
        for (int j = 0; j < 14; j++) {
            float2 f = up2(acc[p][j]);
            a[2*j] = f.x; a[2*j+1] = f.y;
        }
#pragma unroll
        for (int k = 0; k < 9; k++) {
            float ry = a[2*k]   + __ldg(b_om + 2*k);
            float rx = a[2*k+1] + __ldg(b_om + 2*k + 1);
            float rm = a[18+k]  + __ldg(b_om + 18 + k);
            int gi = (b*KK + k)*HW + pix;
            float poy = __ldg(pre_offset + 2*gi + 1);
            float pox = __ldg(pre_offset + 2*gi + 0);
            float ps  = __ldg(pre_sim + gi);

            float py = 10.f*fast_tanh(ry) + poy + (float)(h - 1) + (float)(k/3);
            float px = 10.f*fast_tanh(rx) + pox + (float)(wp_ - 1) + (float)(k%3);
            float m  = fast_sigmoid(rm * ps);

            float fy = floorf(py), fx = floorf(px);
            float dy = py - fy,   dx = px - fx;
            int iy0 = (int)fy, ix0 = (int)fx;
            int iy1 = iy0 + 1, ix1 = ix0 + 1;
            bool vy0 = (unsigned)iy0 < HH, vy1 = (unsigned)iy1 < HH;
            bool vx0 = (unsigned)ix0 < WW, vx1 = (unsigned)ix1 < WW;

            float w00 = (vy0 && vx0) ? (1.f-dy)*(1.f-dx)*m : 0.f;
            float w01 = (vy0 && vx1) ? (1.f-dy)*dx*m       : 0.f;
            float w10 = (vy1 && vx0) ? dy*(1.f-dx)*m       : 0.f;
            float w11 = (vy1 && vx1) ? dy*dx*m             : 0.f;

            int cy0 = min(max(iy0, 0), HH-1), cy1 = min(max(iy1, 0), HH-1);
            int cx0 = min(max(ix0, 0), WW-1), cx1 = min(max(ix1, 0), WW-1);

            g_wts[gi]  = make_float4(w00, w01, w10, w11);
            g_offs[gi] = make_int4(cy0*WW + cx0, cy0*WW + cx1, cy1*WW + cx0, cy1*WW + cx1);
        }
    }
}

// ---------------- kernel 2: double-buffered gather + FFMA2 GEMM ----------------
// Block = 128 threads; tile = 64 px x 64 o; thread tile 4 px x 8 o.
// v smem [p][c] 68-word rows (aligned float4 reads); v & w double-buffered;
// gather(k+1)+stage_w(k+1) overlap GEMM(k); ONE sync per k.
#define SM_V0 0
#define SM_V1 (64*VROW*4)                  // 17408
#define SM_W0 (2*64*VROW*4)                // 34816
#define SM_W1 (SM_W0 + CC*OO*4)            // 51200
#define SM_SZ (SM_W1 + CC*OO*4)            // 67584

__global__ __launch_bounds__(128) void k_main8(
        const float* __restrict__ bias,
        float* __restrict__ out) {
    extern __shared__ char sm[];
    float* vbuf[2] = { (float*)(sm + SM_V0), (float*)(sm + SM_V1) };
    float* wbuf[2] = { (float*)(sm + SM_W0), (float*)(sm + SM_W1) };

    const int tid = threadIdx.x;
    const int bx = blockIdx.x;
    const int h = bx >> 1;
    const int wbase = (bx & 1) << 6;
    const int b = blockIdx.y;
    const int og = tid & 7;          // 8 o-groups of 8
    const int pg = tid >> 3;         // 16 px-groups of 4
    const int c4 = tid & 15;
    const int psub = tid >> 4;       // 0..7
    const float* xb = g_xm + ((size_t)b << 20);

    unsigned long long acc[16];      // [pi(4)][oj(4)] o-pair packed
#pragma unroll
    for (int j = 0; j < 16; j++) acc[j] = 0ULL;

    // ---- helpers as lambdas ----
    auto stage_w = [&](int k, float* wd) {
        const float4* src = (const float4*)(g_wt + (k << 12));
        float4* dst = (float4*)wd;
#pragma unroll
        for (int i = 0; i < 8; i++) dst[(i << 7) + tid] = src[(i << 7) + tid];
    };
    auto gather = [&](int k, float* vd) {
        const int gibase = ((b*KK + k) << 14) + (h << 7) + wbase;
#pragma unroll
        for (int i = 0; i < 8; ++i) {
            int p = (i << 3) + psub;
            float4 wt = __ldg(&g_wts[gibase + p]);
            int4   of = __ldg(&g_offs[gibase + p]);
            int cc = c4 << 2;
            float4 A0 = *(const float4*)(xb + ((size_t)of.x << 6) + cc);
            float4 A1 = *(const float4*)(xb + ((size_t)of.y << 6) + cc);
            float4 A2 = *(const float4*)(xb + ((size_t)of.z << 6) + cc);
            float4 A3 = *(const float4*)(xb + ((size_t)of.w << 6) + cc);
            float4 v;
            v.x = wt.x*A0.x + wt.y*A1.x + wt.z*A2.x + wt.w*A3.x;
            v.y = wt.x*A0.y + wt.y*A1.y + wt.z*A2.y + wt.w*A3.y;
            v.z = wt.x*A0.z + wt.y*A1.z + wt.z*A2.z + wt.w*A3.z;
            v.w = wt.x*A0.w + wt.y*A1.w + wt.z*A2.w + wt.w*A3.w;
            *(float4*)(vd + p*VROW + cc) = v;   // aligned: (68p+4c4)*4B % 16 == 0
        }
    };

    // prologue
    stage_w(0, wbuf[0]);
    gather(0, vbuf[0]);
    __syncthreads();

    for (int k = 0; k < KK; ++k) {
        const int cur = k & 1, nxt = cur ^ 1;
        if (k < KK-1) {
            gather(k + 1, vbuf[nxt]);     // LDG latency hides under GEMM below
            stage_w(k + 1, wbuf[nxt]);
        }
        // GEMM on current buffers
        const float* vs = vbuf[cur];
        const float* wsb = wbuf[cur];
#pragma unroll 4
        for (int q = 0; q < 16; ++q) {     // channel quads
            const int cc = q << 2;
            float4 av0 = *(const float4*)(vs + ((pg << 2) + 0)*VROW + cc);
            float4 av1 = *(const float4*)(vs + ((pg << 2) + 1)*VROW + cc);
            float4 av2 = *(const float4*)(vs + ((pg << 2) + 2)*VROW + cc);
            float4 av3 = *(const float4*)(vs + ((pg << 2) + 3)*VROW + cc);
            const float* a0 = (const float*)&av0;
            const float* a1 = (const float*)&av1;
            const float* a2 = (const float*)&av2;
            const float* a3 = (const float*)&av3;
#pragma unroll
            for (int j = 0; j < 4; ++j) {
                const float* wr = wsb + ((cc + j) << 6) + (og << 3);
                ulonglong2 b01 = *(const ulonglong2*)(wr);
                ulonglong2 b23 = *(const ulonglong2*)(wr + 4);
                unsigned long long d0 = pk2(a0[j], a0[j]);
                unsigned long long d1 = pk2(a1[j], a1[j]);
                unsigned long long d2 = pk2(a2[j], a2[j]);
                unsigned long long d3 = pk2(a3[j], a3[j]);
                fma2(acc[0],  d0, b01.x); fma2(acc[1],  d0, b01.y);
                fma2(acc[2],  d0, b23.x); fma2(acc[3],  d0, b23.y);
                fma2(acc[4],  d1, b01.x); fma2(acc[5],  d1, b01.y);
                fma2(acc[6],  d1, b23.x); fma2(acc[7],  d1, b23.y);
                fma2(acc[8],  d2, b01.x); fma2(acc[9],  d2, b01.y);
                fma2(acc[10], d2, b23.x); fma2(acc[11], d2, b23.y);
                fma2(acc[12], d3, b01.x); fma2(acc[13], d3, b01.y);
                fma2(acc[14], d3, b23.x); fma2(acc[15], d3, b23.y);
            }
        }
        __syncthreads();
    }

    // epilogue: 8 o's x 4 consecutive px per thread
    const int p0 = pg << 2;
    float* ob = out + ((size_t)(b*OO) << 14) + (h << 7) + wbase + p0;
#pragma unroll
    for (int oj = 0; oj < 4; ++oj) {
        int o = (og << 3) + (oj << 1);
        float be = __ldg(bias + o);
        float bo = __ldg(bias + o + 1);
        float2 s0 = up2(acc[0*4 + oj]);
        float2 s1 = up2(acc[1*4 + oj]);
        float2 s2 = up2(acc[2*4 + oj]);
        float2 s3 = up2(acc[3*4 + oj]);
        *(float4*)(ob + ((size_t)o << 14))       = make_float4(s0.x+be, s1.x+be, s2.x+be, s3.x+be);
        *(float4*)(ob + ((size_t)(o + 1) << 14)) = make_float4(s0.y+bo, s1.y+bo, s2.y+bo, s3.y+bo);
    }
}

extern "C" void kernel_launch(void* const* d_in, const int* in_sizes, int n_in,
                              void* d_out, int out_size) {
    const float* x_main     = (const float*)d_in[0];
    const float* x_extra    = (const float*)d_in[1];
    const float* pre_offset = (const float*)d_in[2];
    const float* pre_sim    = (const float*)d_in[3];
    const float* weight     = (const float*)d_in[4];
    const float* bias       = (const float*)d_in[5];
    const float* w_om       = (const float*)d_in[6];
    const float* b_om       = (const float*)d_in[7];
    float* out = (float*)d_out;

    cudaFuncSetAttribute(k_main8, cudaFuncAttributeMaxDynamicSharedMemorySize, SM_SZ);

    k_wt_transpose<<<(KK*CC*OO + 255)/256, 256>>>(weight);
    k_wom_prep<<<(2*32*9*28 + 255)/256, 256>>>(w_om);

    dim3 gt(HW/64, BB);
    k_xm_transpose<<<gt, 256>>>(x_main);

    dim3 g1(WW/16, HH/16, BB);
    k_offset3<<<g1, 128>>>(x_extra, pre_offset, pre_sim, b_om);

    dim3 g2(HH*2, BB);
    k_main8<<<g2, 128, SM_SZ>>>(bias, out);
}

// round 14
// speedup vs baseline: 1.7723x; 1.7723x over previous
#include <cuda_runtime.h>
#include <math.h>
#include <cstdint>

#define HH 128
#define WW 128
#define HW (HH*WW)
#define CC 64
#define OO 64
#define BB 4
#define KK 9
#define VPAD 129

// Scratch (allocation-free rule: __device__ globals)
__device__ float4 g_wts[BB*KK*HW];        // per (b,k,pixel): 4 bilinear corner weights * mask
__device__ int4   g_offs[BB*KK*HW];       // per (b,k,pixel): 4 clamped corner plane-offsets
__device__ float  g_wt[KK*CC*OO];         // weight transposed to [k][c][o]
__device__ float  g_xm[(size_t)BB*HW*CC]; // x_main pixel-major [b][p][c]
__device__ float  g_wom[2*32*9*28];       // w_om pre-staged: [half][(cl*9+t)*28 + oc]

// ---- packed f32x2 helpers ----
__device__ __forceinline__ unsigned long long pk2(float lo, float hi) {
    unsigned long long r;
    asm("mov.b64 %0,{%1,%2};" : "=l"(r) : "f"(lo), "f"(hi));
    return r;
}
__device__ __forceinline__ void fma2(unsigned long long& d, unsigned long long a, unsigned long long b) {
    asm("fma.rn.f32x2 %0,%1,%2,%0;" : "+l"(d) : "l"(a), "l"(b));
}
__device__ __forceinline__ float2 up2(unsigned long long v) {
    float2 r;
    asm("mov.b64 {%0,%1},%2;" : "=f"(r.x), "=f"(r.y) : "l"(v));
    return r;
}
__device__ __forceinline__ float fast_tanh(float x) {
    float e = __expf(2.f * x);
    return 1.f - __fdividef(2.f, e + 1.f);
}
__device__ __forceinline__ float fast_sigmoid(float x) {
    return __fdividef(1.f, 1.f + __expf(-x));
}

// ---------------- kernel 0a: weight transpose [O][C][K] -> [K][C][O] ----------------
__global__ void k_wt_transpose(const float* __restrict__ w) {
    int i = blockIdx.x * 256 + threadIdx.x;
    if (i >= KK*CC*OO) return;
    int k = i >> 12;
    int r = i & 4095;
    int c = r >> 6;
    int o = r & 63;
    g_wt[i] = w[(o*CC + c)*KK + k];
}

// ---------------- kernel 0a': w_om pre-stage into smem-ready layout ----------------
__global__ void k_wom_prep(const float* __restrict__ w_om) {
    int i = blockIdx.x * 256 + threadIdx.x;
    if (i >= 2*32*9*28) return;
    int half = i / (32*9*28);
    int r = i - half*(32*9*28);
    int ct = r / 28;
    int oc = r - ct*28;
    int cl = ct / 9;
    int t  = ct - cl*9;
    float v = 0.f;
    if (oc < 27) v = w_om[(oc*CC + (half*32 + cl))*KK + t];
    g_wom[i] = v;
}

// ---------------- kernel 0b: x_main transpose [C][H][W] -> [H][W][C] ----------------
__global__ __launch_bounds__(256) void k_xm_transpose(const float* __restrict__ x) {
    __shared__ float s[64*68];
    const int tid = threadIdx.x;
    const int b = blockIdx.y;
    const int p0 = blockIdx.x << 6;
#pragma unroll
    for (int i = 0; i < 4; i++) {
        int t = (i << 8) + tid;
        int c = t >> 4, p4 = t & 15;
        float4 v = *(const float4*)(x + (((size_t)b*CC + c) << 14) + p0 + (p4 << 2));
        int base = (p4 << 2)*68 + c;
        s[base] = v.x; s[base+68] = v.y; s[base+136] = v.z; s[base+204] = v.w;
    }
    __syncthreads();
#pragma unroll
    for (int i = 0; i < 4; i++) {
        int t = (i << 8) + tid;
        int p = t >> 4, c4 = t & 15;
        float4 v = *(const float4*)&s[p*68 + (c4 << 2)];
        *(float4*)(g_xm + (((size_t)b << 14) + p0 + p)*CC + (c4 << 2)) = v;
    }
}

// ---------------- kernel 1: offset-mask conv + bilinear prep (fast transcendentals, measured 79.5us) ----------------
__global__ __launch_bounds__(128) void k_offset3(
        const float* __restrict__ x_extra,
        const float* __restrict__ pre_offset,
        const float* __restrict__ pre_sim,
        const float* __restrict__ b_om) {
    __shared__ float ws[32*9*28];
    __shared__ float xt[4*18*20];
    const int tid = threadIdx.x;
    const int b = blockIdx.z;
    const int ty = tid >> 3;
    const int tx = tid & 7;
    const int h  = (blockIdx.y << 4) + ty;
    const int w0 = (blockIdx.x << 4) + (tx << 1);
    const int gy0 = (blockIdx.y << 4) - 1;
    const int gx0 = (blockIdx.x << 4) - 1;

    unsigned long long acc[2][14];
#pragma unroll
    for (int p = 0; p < 2; p++)
#pragma unroll
        for (int j = 0; j < 14; j++) acc[p][j] = 0ULL;

    const float* xb = x_extra + (size_t)b*CC*HW;

    for (int phase = 0; phase < 2; ++phase) {
        __syncthreads();
        {
            const float4* src = (const float4*)(g_wom + phase*(32*9*28));
            float4* dst = (float4*)ws;
            for (int i = tid; i < 32*9*28/4; i += 128) dst[i] = src[i];
        }
        __syncthreads();

        for (int rnd = 0; rnd < 8; ++rnd) {
            if (rnd) __syncthreads();
            for (int idx = tid; idx < 4*324; idx += 128) {
                int cc = idx / 324;
                int rem = idx - cc*324;
                int rr = rem / 18, col = rem - rr*18;
                int gy = gy0 + rr, gx = gx0 + col;
                int c = (phase << 5) + (rnd << 2) + cc;
                xt[cc*360 + rr*20 + col] = ((unsigned)gy < HH && (unsigned)gx < WW)
                    ? __ldg(xb + ((size_t)c << 14) + gy*WW + gx) : 0.f;
            }
            __syncthreads();

#pragma unroll
            for (int cl4 = 0; cl4 < 4; ++cl4) {
                const int cl = (rnd << 2) + cl4;
                float xp[3][4];
                const int base = cl4*360 + ty*20 + (tx << 1);
#pragma unroll
                for (int rr = 0; rr < 3; rr++) {
                    float2 lo = *(const float2*)&xt[base + rr*20];
                    float2 hi = *(const float2*)&xt[base + rr*20 + 2];
                    xp[rr][0] = lo.x; xp[rr][1] = lo.y; xp[rr][2] = hi.x; xp[rr][3] = hi.y;
                }
#pragma unroll
                for (int t = 0; t < 9; t++) {
                    const int tr = t/3, tc = t%3;
                    const ulonglong2* wr = (const ulonglong2*)&ws[(cl*9 + t)*28];
                    ulonglong2 q0 = wr[0], q1 = wr[1], q2 = wr[2];
                    ulonglong2 q3 = wr[3], q4 = wr[4], q5 = wr[5], q6 = wr[6];
                    unsigned long long xd0 = pk2(xp[tr][tc],     xp[tr][tc]);
                    unsigned long long xd1 = pk2(xp[tr][tc + 1], xp[tr][tc + 1]);
                    fma2(acc[0][0],  xd0, q0.x); fma2(acc[0][1],  xd0, q0.y);
                    fma2(acc[0][2],  xd0, q1.x); fma2(acc[0][3],  xd0, q1.y);
                    fma2(acc[0][4],  xd0, q2.x); fma2(acc[0][5],  xd0, q2.y);
                    fma2(acc[0][6],  xd0, q3.x); fma2(acc[0][7],  xd0, q3.y);
                    fma2(acc[0][8],  xd0, q4.x); fma2(acc[0][9],  xd0, q4.y);
                    fma2(acc[0][10], xd0, q5.x); fma2(acc[0][11], xd0, q5.y);
                    fma2(acc[0][12], xd0, q6.x); fma2(acc[0][13], xd0, q6.y);
                    fma2(acc[1][0],  xd1, q0.x); fma2(acc[1][1],  xd1, q0.y);
                    fma2(acc[1][2],  xd1, q1.x); fma2(acc[1][3],  xd1, q1.y);
                    fma2(acc[1][4],  xd1, q2.x); fma2(acc[1][5],  xd1, q2.y);
                    fma2(acc[1][6],  xd1, q3.x); fma2(acc[1][7],  xd1, q3.y);
                    fma2(acc[1][8],  xd1, q4.x); fma2(acc[1][9],  xd1, q4.y);
                    fma2(acc[1][10], xd1, q5.x); fma2(acc[1][11], xd1, q5.y);
                    fma2(acc[1][12], xd1, q6.x); fma2(acc[1][13], xd1, q6.y);
                }
            }
        }
    }

#pragma unroll
    for (int p = 0; p < 2; p++) {
        const int wp_ = w0 + p;
        const int pix = h*WW + wp_;
        float a[28];
#pragma unroll
        for (int j = 0; j < 14; j++) {
            float2 f = up2(acc[p][j]);
            a[2*j] = f.x; a[2*j+1] = f.y;
        }
#pragma unroll
        for (int k = 0; k < 9; k++) {
            float ry = a[2*k]   + __ldg(b_om + 2*k);
            float rx = a[2*k+1] + __ldg(b_om + 2*k + 1);
            float rm = a[18+k]  + __ldg(b_om + 18 + k);
            int gi = (b*KK + k)*HW + pix;
            float poy = __ldg(pre_offset + 2*gi + 1);
            float pox = __ldg(pre_offset + 2*gi + 0);
            float ps  = __ldg(pre_sim + gi);

            float py = 10.f*fast_tanh(ry) + poy + (float)(h - 1) + (float)(k/3);
            float px = 10.f*fast_tanh(rx) + pox + (float)(wp_ - 1) + (float)(k%3);
            float m  = fast_sigmoid(rm * ps);

            float fy = floorf(py), fx = floorf(px);
            float dy = py - fy,   dx = px - fx;
            int iy0 = (int)fy, ix0 = (int)fx;
            int iy1 = iy0 + 1, ix1 = ix0 + 1;
            bool vy0 = (unsigned)iy0 < HH, vy1 = (unsigned)iy1 < HH;
            bool vx0 = (unsigned)ix0 < WW, vx1 = (unsigned)ix1 < WW;

            float w00 = (vy0 && vx0) ? (1.f-dy)*(1.f-dx)*m : 0.f;
            float w01 = (vy0 && vx1) ? (1.f-dy)*dx*m       : 0.f;
            float w10 = (vy1 && vx0) ? dy*(1.f-dx)*m       : 0.f;
            float w11 = (vy1 && vx1) ? dy*dx*m             : 0.f;

            int cy0 = min(max(iy0, 0), HH-1), cy1 = min(max(iy1, 0), HH-1);
            int cx0 = min(max(ix0, 0), WW-1), cx1 = min(max(ix1, 0), WW-1);

            g_wts[gi]  = make_float4(w00, w01, w10, w11);
            g_offs[gi] = make_int4(cy0*WW + cx0, cy0*WW + cx1, cy1*WW + cx0, cy1*WW + cx1);
        }
    }
}

// ---------------- kernel 2: coalesced gather + fma-balanced mini-GEMM (R7, measured ~141us) ----------------
#define SM_V  0
#define SM_W  (CC*VPAD*4)                  // 33024
#define SM_WT (SM_W + CC*OO*4)             // +16384 = 49408
#define SM_OF (SM_WT + 128*16)             // +2048  = 51456
#define SM_SZ (SM_OF + 128*16)             // +2048  = 53504

__global__ __launch_bounds__(128) void k_main4(
        const float* __restrict__ bias,
        float* __restrict__ out) {
    extern __shared__ char sm[];
    float* v_s = (float*)(sm + SM_V);
    float* w_s = (float*)(sm + SM_W);
    float4* wt_s = (float4*)(sm + SM_WT);
    int4*   of_s = (int4*)(sm + SM_OF);

    const int tid = threadIdx.x;
    const int h = blockIdx.x;
    const int b = blockIdx.y;
    const int og = tid & 7;
    const int pg = tid >> 3;
    const float* xb = g_xm + ((size_t)b << 20);

    unsigned long long acc[32];
#pragma unroll
    for (int j = 0; j < 32; j++) acc[j] = 0ULL;

    const int c4 = tid & 15;
    const int psub = tid >> 4;

    for (int k = 0; k < KK; ++k) {
        const int gibase = ((b*KK + k) << 14) + (h << 7);
        wt_s[tid] = __ldg(&g_wts[gibase + tid]);
        of_s[tid] = __ldg(&g_offs[gibase + tid]);
        {
            const float4* src = (const float4*)(g_wt + (k << 12));
            float4* dst = (float4*)w_s;
#pragma unroll
            for (int i = 0; i < 8; i++) dst[(i << 7) + tid] = src[(i << 7) + tid];
        }
        __syncthreads();

#pragma unroll 4
        for (int i = 0; i < 16; ++i) {
            int p = (i << 3) + psub;
            float4 wt = wt_s[p];
            int4   of = of_s[p];
            int cc = c4 << 2;
            float4 A0 = *(const float4*)(xb + ((size_t)of.x << 6) + cc);
            float4 A1 = *(const float4*)(xb + ((size_t)of.y << 6) + cc);
            float4 A2 = *(const float4*)(xb + ((size_t)of.z << 6) + cc);
            float4 A3 = *(const float4*)(xb + ((size_t)of.w << 6) + cc);
            v_s[(cc+0)*VPAD + p] = wt.x*A0.x + wt.y*A1.x + wt.z*A2.x + wt.w*A3.x;
            v_s[(cc+1)*VPAD + p] = wt.x*A0.y + wt.y*A1.y + wt.z*A2.y + wt.w*A3.y;
            v_s[(cc+2)*VPAD + p] = wt.x*A0.z + wt.y*A1.z + wt.z*A2.z + wt.w*A3.z;
            v_s[(cc+3)*VPAD + p] = wt.x*A0.w + wt.y*A1.w + wt.z*A2.w + wt.w*A3.w;
        }
        __syncthreads();

#pragma unroll 4
        for (int c = 0; c < CC; ++c) {
            const float* vr = v_s + c*VPAD + (pg << 3);
            const float* wr = w_s + (c << 6) + (og << 3);
            ulonglong2 b01 = *(const ulonglong2*)(wr);
            ulonglong2 b23 = *(const ulonglong2*)(wr + 4);
            unsigned long long ad[8];
#pragma unroll
            for (int pi = 0; pi < 8; ++pi) ad[pi] = pk2(vr[pi], vr[pi]);
#pragma unroll
            for (int pi = 0; pi < 8; ++pi) {
                fma2(acc[pi*4 + 0], ad[pi], b01.x);
                fma2(acc[pi*4 + 1], ad[pi], b01.y);
                fma2(acc[pi*4 + 2], ad[pi], b23.x);
                fma2(acc[pi*4 + 3], ad[pi], b23.y);
            }
        }
        __syncthreads();
    }

    const int p0 = pg << 3;
    float* ob = out + ((size_t)(b*OO) << 14) + (h << 7) + p0;
#pragma unroll
    for (int oj = 0; oj < 4; ++oj) {
        int o = (og << 3) + (oj << 1);
        float be = __ldg(bias + o);
        float bo = __ldg(bias + o + 1);
        float2 s0 = up2(acc[0*4 + oj]), s1 = up2(acc[1*4 + oj]);
        float2 s2 = up2(acc[2*4 + oj]), s3 = up2(acc[3*4 + oj]);
        float2 s4 = up2(acc[4*4 + oj]), s5 = up2(acc[5*4 + oj]);
        float2 s6 = up2(acc[6*4 + oj]), s7 = up2(acc[7*4 + oj]);
        float* r0 = ob + ((size_t)o << 14);
        float* r1 = ob + ((size_t)(o + 1) << 14);
        *(float4*)(r0)     = make_float4(s0.x+be, s1.x+be, s2.x+be, s3.x+be);
        *(float4*)(r0 + 4) = make_float4(s4.x+be, s5.x+be, s6.x+be, s7.x+be);
        *(float4*)(r1)     = make_float4(s0.y+bo, s1.y+bo, s2.y+bo, s3.y+bo);
        *(float4*)(r1 + 4) = make_float4(s4.y+bo, s5.y+bo, s6.y+bo, s7.y+bo);
    }
}

extern "C" void kernel_launch(void* const* d_in, const int* in_sizes, int n_in,
                              void* d_out, int out_size) {
    const float* x_main     = (const float*)d_in[0];
    const float* x_extra    = (const float*)d_in[1];
    const float* pre_offset = (const float*)d_in[2];
    const float* pre_sim    = (const float*)d_in[3];
    const float* weight     = (const float*)d_in[4];
    const float* bias       = (const float*)d_in[5];
    const float* w_om       = (const float*)d_in[6];
    const float* b_om       = (const float*)d_in[7];
    float* out = (float*)d_out;

    cudaFuncSetAttribute(k_main4, cudaFuncAttributeMaxDynamicSharedMemorySize, SM_SZ);

    k_wt_transpose<<<(KK*CC*OO + 255)/256, 256>>>(weight);
    k_wom_prep<<<(2*32*9*28 + 255)/256, 256>>>(w_om);

    dim3 gt(HW/64, BB);
    k_xm_transpose<<<gt, 256>>>(x_main);

    dim3 g1(WW/16, HH/16, BB);
    k_offset3<<<g1, 128>>>(x_extra, pre_offset, pre_sim, b_om);

    dim3 g2(HH, BB);
    k_main4<<<g2, 128, SM_SZ>>>(bias, out);
}